// round 7
// baseline (speedup 1.0000x reference)
#include <cuda_runtime.h>
#include <cstdint>
#include <math.h>

// ---------------------------------------------------------------------------
// NeuralODE Tsit5 — persistent-CTA fp32 kernel, round 6.
// L1tex-traffic-minimized design (model validated over rounds 1-5):
//   - warp owns 16 exclusive columns x all 32 rows (no split-K, no reduction)
//   - A: one LDS.128 per k -> two packed f32x2 row-pairs, zero movs, 1 wf
//   - W: pre-DUPLICATED in global scratch; ulonglong2 LDG gives (w,w) pairs,
//     zero movs, 128B sectors per warp-k (4x less than R5)
//   - per k per lane: 1 LDS.128 + 2 LDG.128 + 8 ffma2  (issue ~72%)
// ---------------------------------------------------------------------------

#define BATCH   4096
#define DIM     64
#define WIDTH   256
#define NTT     101
#define TM      32
#define NCTA    (BATCH / TM)      // 128
#define THREADS 512

#define ACT_SIZE (WIDTH * TM)     // 8192 floats = 32KB, layout [N][32]
#define ZK_SIZE  (DIM * TM)       // 2048 floats = 8KB,  layout [64][32]

#define SMEM_FLOATS (2*ACT_SIZE + ZK_SIZE + ZK_SIZE + 6*ZK_SIZE)
#define SMEM_BYTES  (SMEM_FLOATS * 4)   // 128KB

// duplicated-W scratch (graph-legal static device memory)
__device__ float g_W0d[DIM   * 2 * WIDTH];   // 64  x 512
__device__ float g_W1d[WIDTH * 2 * WIDTH];   // 256 x 512
__device__ float g_W2d[WIDTH * 2 * WIDTH];   // 256 x 512
__device__ float g_W3d[WIDTH * 2 * DIM];     // 256 x 128

// Tsit5 tableau
__constant__ float c_A[6][5] = {
    {0.f, 0.f, 0.f, 0.f, 0.f},
    {0.161f, 0.f, 0.f, 0.f, 0.f},
    {-0.008480655492356989f, 0.335480655492357f, 0.f, 0.f, 0.f},
    {2.8971530571054935f, -6.359448489975075f, 4.3622954328695815f, 0.f, 0.f},
    {5.325864828439257f, -11.748883564062828f, 7.4955393428898365f, -0.09249506636175525f, 0.f},
    {5.86145544294642f, -12.92096931784711f, 8.159367898576159f, -0.071584973281401f, -0.028269050394068383f}
};
__constant__ float c_B[6] = {
    0.09646076681806523f, 0.01f, 0.4798896504144996f,
    1.379008574103742f, -3.290069515436081f, 2.324710524099774f
};

// ---- packed f32x2 helpers ----
__device__ __forceinline__ unsigned long long pk2(float lo, float hi) {
    unsigned long long r;
    asm("mov.b64 %0, {%1, %2};" : "=l"(r) : "f"(lo), "f"(hi));
    return r;
}
__device__ __forceinline__ void upk2(unsigned long long v, float &lo, float &hi) {
    asm("mov.b64 {%0, %1}, %2;" : "=f"(lo), "=f"(hi) : "l"(v));
}
__device__ __forceinline__ void ffma2(unsigned long long &d,
                                      unsigned long long a,
                                      unsigned long long b) {
    asm("fma.rn.f32x2 %0, %1, %2, %0;" : "+l"(d) : "l"(a), "l"(b));
}

// ---------------------------------------------------------------------------
// Prologue: duplicate every W element (pairs adjacent): dst[2i]=dst[2i+1]=src[i]
// ---------------------------------------------------------------------------
__global__ void dup_kernel(const float *__restrict__ W0, const float *__restrict__ W1,
                           const float *__restrict__ W2, const float *__restrict__ W3) {
    int i = blockIdx.x * blockDim.x + threadIdx.x;
    const int n0 = DIM * WIDTH;        // 16384
    const int n1 = WIDTH * WIDTH;      // 65536
    if (i < n0) {
        float v = W0[i]; g_W0d[2*i] = v; g_W0d[2*i+1] = v;
    } else if (i < n0 + n1) {
        int j = i - n0;
        float v = W1[j]; g_W1d[2*j] = v; g_W1d[2*j+1] = v;
    } else if (i < n0 + 2*n1) {
        int j = i - n0 - n1;
        float v = W2[j]; g_W2d[2*j] = v; g_W2d[2*j+1] = v;
    } else if (i < 2*n0 + 2*n1) {
        int j = i - n0 - 2*n1;
        float v = W3[j]; g_W3d[2*j] = v; g_W3d[2*j+1] = v;
    }
}

// ---------------------------------------------------------------------------
// Dense layer:  Aout[c][r] = act( sum_k Wd[k][2c] * Ain[k][r] + b[c] )
// Ain/Aout: SMEM, transposed [n*32 + m] (no swizzle needed).
// N=256: warp owns cols [w*16, w*16+16); lane: rows (lane&7)*4..+3,
//        cols w*16+(lane>>3)*4..+3.  8 ffma2 / k.
// N=64 : warp owns cols [w*4, w*4+4); lane: rows (lane&15)*2..+1,
//        cols w*4+(lane>>4)*2..+1.   2 ffma2 / k.
// Ends with __syncthreads (epilogue visible to next layer).
// ---------------------------------------------------------------------------
template <int K, int N, bool ACT>
__device__ __forceinline__ void layerT(const float *Ain, float *Aout,
                                       const float *__restrict__ Wd,
                                       const float *__restrict__ bg) {
    const int tid  = threadIdx.x;
    const int w    = tid >> 5;
    const int lane = tid & 31;

    if constexpr (N == 256) {
        const int r0 = (lane & 7) * 4;
        const int c0 = w * 16 + (lane >> 3) * 4;

        unsigned long long acc[2][4];
#pragma unroll
        for (int c = 0; c < 4; c++) {
            float b = __ldg(bg + c0 + c);
            unsigned long long bb = pk2(b, b);
            acc[0][c] = bb;
            acc[1][c] = bb;
        }

        const float *Ap = Ain + r0;
        const float *Wp = Wd + 2 * c0;

        ulonglong2 a_cur = *reinterpret_cast<const ulonglong2 *>(Ap);
        ulonglong2 w_c0  = __ldg(reinterpret_cast<const ulonglong2 *>(Wp));
        ulonglong2 w_c1  = __ldg(reinterpret_cast<const ulonglong2 *>(Wp + 4));
        Ap += TM;
        Wp += 2 * N;

#pragma unroll 4
        for (int k = 0; k < K - 1; ++k) {
            ulonglong2 a_nxt = *reinterpret_cast<const ulonglong2 *>(Ap);
            ulonglong2 w_n0  = __ldg(reinterpret_cast<const ulonglong2 *>(Wp));
            ulonglong2 w_n1  = __ldg(reinterpret_cast<const ulonglong2 *>(Wp + 4));
            Ap += TM;
            Wp += 2 * N;

            ffma2(acc[0][0], a_cur.x, w_c0.x);
            ffma2(acc[1][0], a_cur.y, w_c0.x);
            ffma2(acc[0][1], a_cur.x, w_c0.y);
            ffma2(acc[1][1], a_cur.y, w_c0.y);
            ffma2(acc[0][2], a_cur.x, w_c1.x);
            ffma2(acc[1][2], a_cur.y, w_c1.x);
            ffma2(acc[0][3], a_cur.x, w_c1.y);
            ffma2(acc[1][3], a_cur.y, w_c1.y);

            a_cur = a_nxt;
            w_c0 = w_n0;
            w_c1 = w_n1;
        }
        // last k
        ffma2(acc[0][0], a_cur.x, w_c0.x);
        ffma2(acc[1][0], a_cur.y, w_c0.x);
        ffma2(acc[0][1], a_cur.x, w_c0.y);
        ffma2(acc[1][1], a_cur.y, w_c0.y);
        ffma2(acc[0][2], a_cur.x, w_c1.x);
        ffma2(acc[1][2], a_cur.y, w_c1.x);
        ffma2(acc[0][3], a_cur.x, w_c1.y);
        ffma2(acc[1][3], a_cur.y, w_c1.y);

        // epilogue: tanh + packed STS.64 per (row-pair, col)
#pragma unroll
        for (int rp = 0; rp < 2; rp++) {
#pragma unroll
            for (int c = 0; c < 4; c++) {
                float x0, x1;
                upk2(acc[rp][c], x0, x1);
                if (ACT) { x0 = tanhf(x0); x1 = tanhf(x1); }
                float2 v; v.x = x0; v.y = x1;
                *reinterpret_cast<float2 *>(Aout + (c0 + c) * TM + r0 + 2 * rp) = v;
            }
        }
    } else {
        // N == 64
        const int r0 = (lane & 15) * 2;
        const int c0 = w * 4 + (lane >> 4) * 2;

        unsigned long long acc[2];
        {
            float b0v = __ldg(bg + c0);
            float b1v = __ldg(bg + c0 + 1);
            acc[0] = pk2(b0v, b0v);
            acc[1] = pk2(b1v, b1v);
        }

        const float *Ap = Ain + r0;
        const float *Wp = Wd + 2 * c0;

        unsigned long long a_cur = *reinterpret_cast<const unsigned long long *>(Ap);
        ulonglong2 w_c = __ldg(reinterpret_cast<const ulonglong2 *>(Wp));
        Ap += TM;
        Wp += 2 * N;

#pragma unroll 8
        for (int k = 0; k < K - 1; ++k) {
            unsigned long long a_nxt = *reinterpret_cast<const unsigned long long *>(Ap);
            ulonglong2 w_n = __ldg(reinterpret_cast<const ulonglong2 *>(Wp));
            Ap += TM;
            Wp += 2 * N;

            ffma2(acc[0], a_cur, w_c.x);
            ffma2(acc[1], a_cur, w_c.y);

            a_cur = a_nxt;
            w_c = w_n;
        }
        ffma2(acc[0], a_cur, w_c.x);
        ffma2(acc[1], a_cur, w_c.y);

#pragma unroll
        for (int c = 0; c < 2; c++) {
            float x0, x1;
            upk2(acc[c], x0, x1);
            if (ACT) { x0 = tanhf(x0); x1 = tanhf(x1); }
            float2 v; v.x = x0; v.y = x1;
            *reinterpret_cast<float2 *>(Aout + (c0 + c) * TM + r0) = v;
        }
    }
    __syncthreads();
}

// ---------------------------------------------------------------------------
__global__ void __launch_bounds__(THREADS, 1)
node_kernel(const float *__restrict__ ts, const float *__restrict__ y0,
            const float *__restrict__ b0, const float *__restrict__ b1,
            const float *__restrict__ b2, const float *__restrict__ b3,
            float *__restrict__ out) {
    extern __shared__ float sm[];
    float *actA = sm;                       // [256][32]
    float *actB = actA + ACT_SIZE;
    float *zbuf = actB + ACT_SIZE;          // [64][32]
    float *ybuf = zbuf + ZK_SIZE;
    float *kbuf = ybuf + ZK_SIZE;           // 6 * [64][32]

    const int tid = threadIdx.x;
    const int cta = blockIdx.x;

    // ingest y0 (row-major) -> ybuf (transposed); emit out[0]
    {
        const float *y0c = y0 + (size_t)cta * TM * DIM;
        float *o0 = out + (size_t)cta * TM * DIM;
        for (int i = tid; i < TM * DIM; i += THREADS) {
            const int r = i >> 6;
            const int d = i & 63;
            float v = __ldg(y0c + i);
            ybuf[d * TM + r] = v;
            o0[i] = v;
        }
    }
    __syncthreads();

    for (int t = 1; t < NTT; ++t) {
        const float h = __ldg(ts + t) - __ldg(ts + t - 1);

        for (int s = 0; s < 6; ++s) {
            const float *zin;
            if (s == 0) {
                zin = ybuf;
            } else {
                // z = y + h * sum_{j<s} A[s][j]*k_j  (elementwise)
                float4 *zb = reinterpret_cast<float4 *>(zbuf);
                const float4 *yb = reinterpret_cast<const float4 *>(ybuf);
                for (int i = tid; i < ZK_SIZE / 4; i += THREADS) {
                    float4 v = yb[i];
                    for (int j = 0; j < s; j++) {
                        float c = h * c_A[s][j];
                        float4 kv = reinterpret_cast<const float4 *>(kbuf + j * ZK_SIZE)[i];
                        v.x += c * kv.x; v.y += c * kv.y;
                        v.z += c * kv.z; v.w += c * kv.w;
                    }
                    zb[i] = v;
                }
                __syncthreads();
                zin = zbuf;
            }

            layerT<DIM,   WIDTH, true >(zin,  actA, g_W0d, b0);
            layerT<WIDTH, WIDTH, true >(actA, actB, g_W1d, b1);
            layerT<WIDTH, WIDTH, true >(actB, actA, g_W2d, b2);
            layerT<WIDTH, DIM,   false>(actA, kbuf + s * ZK_SIZE, g_W3d, b3);
        }

        // y += h * sum_j B[j]*k_j  (elementwise)
        {
            float4 *yb = reinterpret_cast<float4 *>(ybuf);
            for (int i = tid; i < ZK_SIZE / 4; i += THREADS) {
                float4 v = yb[i];
#pragma unroll
                for (int j = 0; j < 6; j++) {
                    float c = h * c_B[j];
                    float4 kv = reinterpret_cast<const float4 *>(kbuf + j * ZK_SIZE)[i];
                    v.x += c * kv.x; v.y += c * kv.y;
                    v.z += c * kv.z; v.w += c * kv.w;
                }
                yb[i] = v;
            }
        }
        __syncthreads();

        // store out[t] (row-major, coalesced) from ybuf
        {
            float *outc = out + (size_t)t * (BATCH * DIM) + (size_t)cta * TM * DIM;
            for (int i = tid; i < TM * DIM; i += THREADS) {
                const int r = i >> 6;
                const int d = i & 63;
                outc[i] = ybuf[d * TM + r];
            }
        }
        __syncthreads();
    }
}

// ---------------------------------------------------------------------------
extern "C" void kernel_launch(void *const *d_in, const int *in_sizes, int n_in,
                              void *d_out, int out_size) {
    const float *ts = (const float *)d_in[0];
    const float *y0 = (const float *)d_in[1];
    const float *W0 = (const float *)d_in[2];
    const float *b0 = (const float *)d_in[3];
    const float *W1 = (const float *)d_in[4];
    const float *b1 = (const float *)d_in[5];
    const float *W2 = (const float *)d_in[6];
    const float *b2 = (const float *)d_in[7];
    const float *W3 = (const float *)d_in[8];
    const float *b3 = (const float *)d_in[9];
    float *out = (float *)d_out;

    // prologue: build duplicated W (2*16384 + 2*65536 = 163840 elements)
    dup_kernel<<<(163840 + 255) / 256, 256>>>(W0, W1, W2, W3);

    cudaFuncSetAttribute(node_kernel,
                         cudaFuncAttributeMaxDynamicSharedMemorySize, SMEM_BYTES);
    node_kernel<<<NCTA, THREADS, SMEM_BYTES>>>(ts, y0, b0, b1, b2, b3, out);
}

// round 8
// speedup vs baseline: 1.7470x; 1.7470x over previous
#include <cuda_runtime.h>
#include <cstdint>
#include <math.h>

// ---------------------------------------------------------------------------
// NeuralODE Tsit5 — persistent-CTA fp32 kernel, round 7.
// Wavefront-engineered GEMM (model validated R1-R6):
//   A: [k][32] row-swizzled SMEM -> 2x LDS.128 same-address broadcasts (2 wf)
//   W: cp.async double-buffered SMEM tiles, chunk-swizzled -> conflict-free
//      lane-strided 2x LDS.128 (8 wf)
//   per warp-k: 10 wf / 32 ffma2 (64 FMA-cyc) -> FMA-bound
//   split-K=4 with 3-phase SMEM reduction (red1 aliases act; extra sync)
// ---------------------------------------------------------------------------

#define BATCH   4096
#define DIM     64
#define WIDTH   256
#define NTT     101
#define TM      32
#define NCTA    (BATCH / TM)      // 128
#define THREADS 512

// row swizzle for activation/partial buffers: element (idx, r) at r ^ SWR(idx)
#define SWR(idx) ((((idx) >> 3) & 7) << 2)
// chunk swizzle for W tiles (16B chunks within a row)
__device__ __forceinline__ int swc(int j) { return j ^ ((j >> 3) & 7); }

#define ACT_SIZE (WIDTH * TM)     // 8192 floats
#define ZK_SIZE  (DIM * TM)       // 2048 floats
#define WTILE_F  (32 * WIDTH)     // 8192 floats per 32-row tile (32KB)

#define SMEM_FLOATS (ACT_SIZE + ACT_SIZE + 2*WTILE_F + ZK_SIZE + ZK_SIZE + 6*ZK_SIZE)
#define SMEM_BYTES  (SMEM_FLOATS * 4)   // 192KB

// Tsit5 tableau
__constant__ float c_A[6][5] = {
    {0.f, 0.f, 0.f, 0.f, 0.f},
    {0.161f, 0.f, 0.f, 0.f, 0.f},
    {-0.008480655492356989f, 0.335480655492357f, 0.f, 0.f, 0.f},
    {2.8971530571054935f, -6.359448489975075f, 4.3622954328695815f, 0.f, 0.f},
    {5.325864828439257f, -11.748883564062828f, 7.4955393428898365f, -0.09249506636175525f, 0.f},
    {5.86145544294642f, -12.92096931784711f, 8.159367898576159f, -0.071584973281401f, -0.028269050394068383f}
};
__constant__ float c_B[6] = {
    0.09646076681806523f, 0.01f, 0.4798896504144996f,
    1.379008574103742f, -3.290069515436081f, 2.324710524099774f
};

// ---- packed f32x2 helpers ----
__device__ __forceinline__ unsigned long long pk2(float lo, float hi) {
    unsigned long long r;
    asm("mov.b64 %0, {%1, %2};" : "=l"(r) : "f"(lo), "f"(hi));
    return r;
}
__device__ __forceinline__ void upk2(unsigned long long v, float &lo, float &hi) {
    asm("mov.b64 {%0, %1}, %2;" : "=f"(lo), "=f"(hi) : "l"(v));
}
__device__ __forceinline__ void ffma2(unsigned long long &d,
                                      unsigned long long a,
                                      unsigned long long b) {
    asm("fma.rn.f32x2 %0, %1, %2, %0;" : "+l"(d) : "l"(a), "l"(b));
}

// ---- cp.async helpers ----
__device__ __forceinline__ void cpa16(float *smem_dst, const float *gmem_src) {
    unsigned s = (unsigned)__cvta_generic_to_shared(smem_dst);
    asm volatile("cp.async.cg.shared.global [%0], [%1], 16;" :: "r"(s), "l"(gmem_src));
}
__device__ __forceinline__ void cpa_commit() {
    asm volatile("cp.async.commit_group;");
}
__device__ __forceinline__ void cpa_wait_all() {
    asm volatile("cp.async.wait_group 0;");
}

// ---------------------------------------------------------------------------
// Copy W tile t into SMEM (chunk-swizzled). Tile = 4 sub-tiles (one per
// k-slice) of 8 rows x N cols. Source row for (slice s, local kk):
//   s*(K/4) + t*8 + kk.
// ---------------------------------------------------------------------------
template <int K, int N>
__device__ __forceinline__ void copy_tile(float *dst, const float *__restrict__ Wg, int t) {
    constexpr int CPR    = N / 4;        // 16B chunks per row
    constexpr int CHUNKS = 32 * CPR;     // chunks per tile
#pragma unroll
    for (int m = threadIdx.x; m < CHUNKS; m += THREADS) {
        const int row = m / CPR;         // 0..31
        const int j   = m % CPR;
        const int s   = row >> 3;
        const int kk  = row & 7;
        const float *src = Wg + (size_t)(s * (K / 4) + t * 8 + kk) * N + j * 4;
        cpa16(dst + (size_t)row * N + swc(j) * 4, src);
    }
}

// ---------------------------------------------------------------------------
// Dense layer with split-K=4:
//   Aout[c][r^SWR(c)] = act( sum_k W[k][c] * Ain[k][r^SWR(k)] + b[c] )
// Warp w: ks = w>>2 (k-slice), rg = w&3 (rows rg*8..rg*8+7).
// Lane: CPL = N/32 columns at lane*CPL.
// red1 MAY alias Ain (act buffer): SYNC-A before phase-1 stores makes it safe.
// ---------------------------------------------------------------------------
template <int K, int N, bool ACT>
__device__ __forceinline__ void layerT(const float *Ain, float *Aout,
                                       const float *__restrict__ Wg,
                                       const float *__restrict__ bg,
                                       float *wbuf, float *red0, float *red1) {
    constexpr int CPL   = N / 32;        // 8 or 2
    constexpr int TILES = K / 32;
    constexpr int KSLEN = K / 4;

    const int tid  = threadIdx.x;
    const int w    = tid >> 5;
    const int lane = tid & 31;
    const int ks   = w >> 2;
    const int rg   = w & 3;
    const int r0   = rg * 8;
    const int c0   = lane * CPL;

    // hoisted swizzled W offsets (floats)
    int wo0, wo1;
    if constexpr (CPL == 8) {
        wo0 = swc(2 * lane) * 4;
        wo1 = swc(2 * lane + 1) * 4;
    } else {
        wo0 = swc(lane >> 1) * 4 + (lane & 1) * 2;
        wo1 = 0;
    }

    unsigned long long acc[4][CPL];
    if (ks == 0) {
#pragma unroll
        for (int c = 0; c < CPL; c++) {
            float b = __ldg(bg + c0 + c);
            unsigned long long bb = pk2(b, b);
#pragma unroll
            for (int p = 0; p < 4; p++) acc[p][c] = bb;
        }
    } else {
#pragma unroll
        for (int p = 0; p < 4; p++)
#pragma unroll
            for (int c = 0; c < CPL; c++) acc[p][c] = 0ull;
    }

    // prologue: tile 0
    copy_tile<K, N>(wbuf, Wg, 0);
    cpa_commit();

    for (int t = 0; t < TILES; ++t) {
        cpa_wait_all();
        __syncthreads();
        if (t + 1 < TILES) {
            copy_tile<K, N>(wbuf + ((t + 1) & 1) * WTILE_F, Wg, t + 1);
            cpa_commit();
        }

        const float *wt = wbuf + (t & 1) * WTILE_F + (size_t)(ks * 8) * N;
        const int kbase = ks * KSLEN + t * 8;
        const int swk   = SWR(kbase);          // constant across the tile's 8 k
        const float *a0 = Ain + kbase * TM + (r0 ^ swk);
        const float *a1 = Ain + kbase * TM + ((r0 + 4) ^ swk);

#pragma unroll
        for (int kk = 0; kk < 8; ++kk) {
            // A: rows r0..r0+7 of column k as packed pairs (2 broadcast LDS.128)
            ulonglong2 A0 = *reinterpret_cast<const ulonglong2 *>(a0 + kk * TM);
            ulonglong2 A1 = *reinterpret_cast<const ulonglong2 *>(a1 + kk * TM);

            const float *wr = wt + kk * N;
            float wv[CPL];
            if constexpr (CPL == 8) {
                float4 x = *reinterpret_cast<const float4 *>(wr + wo0);
                float4 y = *reinterpret_cast<const float4 *>(wr + wo1);
                wv[0]=x.x; wv[1]=x.y; wv[2]=x.z; wv[3]=x.w;
                wv[4]=y.x; wv[5]=y.y; wv[6]=y.z; wv[7]=y.w;
            } else {
                float2 x = *reinterpret_cast<const float2 *>(wr + wo0);
                wv[0]=x.x; wv[1]=x.y;
            }

#pragma unroll
            for (int c = 0; c < CPL; c++) {
                unsigned long long wp = pk2(wv[c], wv[c]);
                ffma2(acc[0][c], A0.x, wp);
                ffma2(acc[1][c], A0.y, wp);
                ffma2(acc[2][c], A1.x, wp);
                ffma2(acc[3][c], A1.y, wp);
            }
        }
    }

    // SYNC-A: all k-loop reads (Ain, wbuf) complete before red1(=act) writes
    __syncthreads();

    // phase 1: ks2 -> red0, ks3 -> red1
    if (ks >= 2) {
        float *dst = (ks == 2) ? red0 : red1;
#pragma unroll
        for (int c = 0; c < CPL; c++) {
            const int cc = c0 + c;
            const int sc = SWR(cc);
            float *base = dst + cc * TM;
#pragma unroll
            for (int q = 0; q < 2; q++) {
                float a0v, a1v, a2v, a3v;
                upk2(acc[2*q][c],   a0v, a1v);
                upk2(acc[2*q+1][c], a2v, a3v);
                float4 v; v.x=a0v; v.y=a1v; v.z=a2v; v.w=a3v;
                *reinterpret_cast<float4 *>(base + ((r0 + 4*q) ^ sc)) = v;
            }
        }
    }
    __syncthreads();

    // phase 2: ks1: acc + red0 + red1 -> red0
    if (ks == 1) {
#pragma unroll
        for (int c = 0; c < CPL; c++) {
            const int cc = c0 + c;
            const int sc = SWR(cc);
            float *b0p = red0 + cc * TM;
            const float *b1p = red1 + cc * TM;
#pragma unroll
            for (int q = 0; q < 2; q++) {
                const int off = (r0 + 4*q) ^ sc;
                float4 v0 = *reinterpret_cast<const float4 *>(b0p + off);
                float4 v1 = *reinterpret_cast<const float4 *>(b1p + off);
                float a0v, a1v, a2v, a3v;
                upk2(acc[2*q][c],   a0v, a1v);
                upk2(acc[2*q+1][c], a2v, a3v);
                float4 v;
                v.x = a0v + v0.x + v1.x;
                v.y = a1v + v0.y + v1.y;
                v.z = a2v + v0.z + v1.z;
                v.w = a3v + v0.w + v1.w;
                *reinterpret_cast<float4 *>(b0p + off) = v;
            }
        }
    }
    __syncthreads();

    // phase 3: ks0: acc + red0 (+bias already), tanh -> Aout
    if (ks == 0) {
#pragma unroll
        for (int c = 0; c < CPL; c++) {
            const int cc = c0 + c;
            const int sc = SWR(cc);
            const float *b0p = red0 + cc * TM;
            float *dst = Aout + cc * TM;
#pragma unroll
            for (int q = 0; q < 2; q++) {
                const int off = (r0 + 4*q) ^ sc;
                float4 v0 = *reinterpret_cast<const float4 *>(b0p + off);
                float a0v, a1v, a2v, a3v;
                upk2(acc[2*q][c],   a0v, a1v);
                upk2(acc[2*q+1][c], a2v, a3v);
                float4 v;
                v.x = a0v + v0.x;
                v.y = a1v + v0.y;
                v.z = a2v + v0.z;
                v.w = a3v + v0.w;
                if (ACT) {
                    v.x = tanhf(v.x); v.y = tanhf(v.y);
                    v.z = tanhf(v.z); v.w = tanhf(v.w);
                }
                *reinterpret_cast<float4 *>(dst + off) = v;
            }
        }
    }
    __syncthreads();
}

// ---------------------------------------------------------------------------
__global__ void __launch_bounds__(THREADS, 1)
node_kernel(const float *__restrict__ ts, const float *__restrict__ y0,
            const float *__restrict__ W0, const float *__restrict__ b0,
            const float *__restrict__ W1, const float *__restrict__ b1,
            const float *__restrict__ W2, const float *__restrict__ b2,
            const float *__restrict__ W3, const float *__restrict__ b3,
            float *__restrict__ out) {
    extern __shared__ float sm[];
    float *act  = sm;                    // 8192, [256][32] row-swizzled
    float *red0 = act + ACT_SIZE;        // 8192
    float *wbuf = red0 + ACT_SIZE;       // 16384 (2 tiles)
    float *zbuf = wbuf + 2 * WTILE_F;    // 2048, [64][32] row-swizzled
    float *ybuf = zbuf + ZK_SIZE;        // 2048
    float *kbuf = ybuf + ZK_SIZE;        // 6 * 2048
    float *red1 = act;                   // aliases act (safe: SYNC-A)

    const int tid = threadIdx.x;
    const int cta = blockIdx.x;

    // ingest y0 (row-major) -> ybuf (transposed, row-swizzled); emit out[0]
    {
        const float *y0c = y0 + (size_t)cta * TM * DIM;
        float *o0 = out + (size_t)cta * TM * DIM;
        for (int i = tid; i < TM * DIM; i += THREADS) {
            const int r = i >> 6;
            const int d = i & 63;
            float v = __ldg(y0c + i);
            ybuf[d * TM + (r ^ SWR(d))] = v;
            o0[i] = v;
        }
    }
    __syncthreads();

    for (int t = 1; t < NTT; ++t) {
        const float h = __ldg(ts + t) - __ldg(ts + t - 1);

        for (int s = 0; s < 6; ++s) {
            const float *zin;
            if (s == 0) {
                zin = ybuf;
            } else {
                // z = y + h * sum_{j<s} A[s][j]*k_j (elementwise, same layout)
                float4 *zb = reinterpret_cast<float4 *>(zbuf);
                const float4 *yb = reinterpret_cast<const float4 *>(ybuf);
                for (int i = tid; i < ZK_SIZE / 4; i += THREADS) {
                    float4 v = yb[i];
                    for (int j = 0; j < s; j++) {
                        float c = h * c_A[s][j];
                        float4 kv = reinterpret_cast<const float4 *>(kbuf + j * ZK_SIZE)[i];
                        v.x += c * kv.x; v.y += c * kv.y;
                        v.z += c * kv.z; v.w += c * kv.w;
                    }
                    zb[i] = v;
                }
                __syncthreads();
                zin = zbuf;
            }

            layerT<DIM,   WIDTH, true >(zin, act, W0, b0, wbuf, red0, red1);
            layerT<WIDTH, WIDTH, true >(act, act, W1, b1, wbuf, red0, red1);
            layerT<WIDTH, WIDTH, true >(act, act, W2, b2, wbuf, red0, red1);
            layerT<WIDTH, DIM,   false>(act, kbuf + s * ZK_SIZE, W3, b3, wbuf, red0, red1);
        }

        // y += h * sum_j B[j]*k_j (elementwise)
        {
            float4 *yb = reinterpret_cast<float4 *>(ybuf);
            for (int i = tid; i < ZK_SIZE / 4; i += THREADS) {
                float4 v = yb[i];
#pragma unroll
                for (int j = 0; j < 6; j++) {
                    float c = h * c_B[j];
                    float4 kv = reinterpret_cast<const float4 *>(kbuf + j * ZK_SIZE)[i];
                    v.x += c * kv.x; v.y += c * kv.y;
                    v.z += c * kv.z; v.w += c * kv.w;
                }
                yb[i] = v;
            }
        }
        __syncthreads();

        // store out[t] (row-major, coalesced) from swizzled ybuf
        {
            float *outc = out + (size_t)t * (BATCH * DIM) + (size_t)cta * TM * DIM;
            for (int i = tid; i < TM * DIM; i += THREADS) {
                const int r = i >> 6;
                const int d = i & 63;
                outc[i] = ybuf[d * TM + (r ^ SWR(d))];
            }
        }
        __syncthreads();
    }
}

// ---------------------------------------------------------------------------
extern "C" void kernel_launch(void *const *d_in, const int *in_sizes, int n_in,
                              void *d_out, int out_size) {
    const float *ts = (const float *)d_in[0];
    const float *y0 = (const float *)d_in[1];
    const float *W0 = (const float *)d_in[2];
    const float *b0 = (const float *)d_in[3];
    const float *W1 = (const float *)d_in[4];
    const float *b1 = (const float *)d_in[5];
    const float *W2 = (const float *)d_in[6];
    const float *b2 = (const float *)d_in[7];
    const float *W3 = (const float *)d_in[8];
    const float *b3 = (const float *)d_in[9];
    float *out = (float *)d_out;

    cudaFuncSetAttribute(node_kernel,
                         cudaFuncAttributeMaxDynamicSharedMemorySize, SMEM_BYTES);
    node_kernel<<<NCTA, THREADS, SMEM_BYTES>>>(ts, y0, W0, b0, W1, b1,
                                               W2, b2, W3, b3, out);
}